// round 4
// baseline (speedup 1.0000x reference)
#include <cuda_runtime.h>

// ---------------------------------------------------------------------------
// TT-Embedding on GB300 (sm_103a):
//   IN_MODES (40,32,25) -> V=32000;  OUT_MODES (8,8,16) -> E=1024; ranks 16,16
//   out[t,e], e = xy*16 + z;  v -> (p = v/800, q = (v/25)%32, r = v%25)
//   PQ[p,q][xy][c] = sum_b core0[x,p,b]*core1[b,y,q,c]   (5.24 MB, L2-resident)
//   out = PQ_slice (64x16) @ M2_r (16x16)   per token
// Two kernels only: build (with folded int64-detect, self-resetting) + gather.
// ---------------------------------------------------------------------------

#define NP 40
#define NQ 32
#define NR 25

__device__ float    g_PQ[NP * NQ * 1024];   // [pq][xy*16 + c]
__device__ int      g_is64;
__device__ unsigned g_cnt;                  // self-resets via atomicInc wrap
__device__ int      g_part[64];

// ---------------------------------------------------------------------------
// Kernel 1: build PQ table + int64 detection (first n_det blocks).
//   core0: (1,8,40,16)  c0[(x*40+p)*16+b]
//   core1: (16,8,32,16) c1[by*512 + q*16 + c]
// ---------------------------------------------------------------------------
__global__ __launch_bounds__(256) void tt_build_pq_kernel(
    const float* __restrict__ c0, const float* __restrict__ c1,
    const unsigned* __restrict__ idw, int n_pairs, int n_det)
{
    const int tid = threadIdx.x;
    const int pq  = blockIdx.x;

    // ---- folded detection over first n_pairs (lo,hi) word pairs ----------
    if (pq < n_det) {
        int j   = pq * 256 + tid;
        int bad = (j < n_pairs) && (idw[2 * j + 1] != 0u);
        unsigned m = __ballot_sync(0xffffffffu, bad);
        __shared__ int s_any;
        if (tid == 0) s_any = 0;
        __syncthreads();
        if ((tid & 31) == 0 && m) s_any = 1;
        __syncthreads();
        if (tid == 0) {
            g_part[pq] = s_any;
            __threadfence();
            unsigned old = atomicInc(&g_cnt, (unsigned)(n_det - 1)); // wraps -> 0
            if (old == (unsigned)(n_det - 1)) {
                int any = 0;
                for (int i = 0; i < n_det; i++) any |= ((volatile int*)g_part)[i];
                g_is64 = !any;
            }
        }
    }

    // ---- main PQ build ----------------------------------------------------
    const int p = pq / NQ;
    const int q = pq % NQ;

    __shared__ float sA[8 * 16];     // A[x][b]
    __shared__ float sM1[128 * 16];  // M1[(b*8+y)][c]

    if (tid < 128) {
        int x = tid >> 4, b = tid & 15;
        sA[tid] = c0[(x * NP + p) * 16 + b];
    }
    #pragma unroll
    for (int i = tid; i < 2048; i += 256) {
        int by = i >> 4, c = i & 15;
        sM1[i] = c1[by * 512 + q * 16 + c];
    }
    __syncthreads();

    #pragma unroll
    for (int k = 0; k < 4; k++) {
        int o  = tid + 256 * k;       // o = xy*16 + c
        int xy = o >> 4;
        int c  = o & 15;
        int x  = xy >> 3;
        int y  = xy & 7;
        float s = 0.f;
        #pragma unroll
        for (int b = 0; b < 16; b++)
            s = fmaf(sA[x * 16 + b], sM1[(b * 8 + y) * 16 + c], s);
        g_PQ[pq * 1024 + o] = s;
    }
}

// ---------------------------------------------------------------------------
// Kernel 2: gather. One block per token, 256 threads.
//   core2: (16,16,25)  c2[(c*16+z)*25 + r]
// Thread tid -> xy = tid>>2, z-quad = tid&3 -> 4 consecutive outputs,
// one STG.128 at float4 slot index == tid (perfectly coalesced).
// ---------------------------------------------------------------------------
#define PQ_STRIDE 20   // padded row stride (floats): bank-conflict-free reads

__global__ __launch_bounds__(256) void tt_gather_kernel(
    const float* __restrict__ c2, const unsigned* __restrict__ idw,
    float* __restrict__ out)
{
    const int t   = blockIdx.x;
    const int tid = threadIdx.x;

    // vocab < 2^31 -> low 32-bit word is always sufficient
    const unsigned u = g_is64 ? idw[2 * t] : idw[t];
    const unsigned p = u / 800u;
    const unsigned q = (u / 25u) % 32u;
    const unsigned r = u % 25u;

    __shared__ float sPQ[64 * PQ_STRIDE];   // padded rows [xy][c]
    __shared__ float sM2[256];              // [c*16 + z]

    // stage PQ slice (coalesced LDG.128) and M2 column for this r
    const float4* src = (const float4*)(g_PQ + (p * NQ + q) * 1024);
    float4 pv = src[tid];
    sM2[tid]  = __ldg(&c2[tid * 25 + r]);   // tid == c*16+z exactly
    ((float4*)(sPQ + (tid >> 2) * PQ_STRIDE))[tid & 3] = pv;
    __syncthreads();

    const int xy = tid >> 2;
    const int zq = tid & 3;
    const float* rowp = sPQ + xy * PQ_STRIDE;
    const float* mb   = sM2 + zq * 4;

    unsigned long long acc01 = 0ull, acc23 = 0ull;   // {+0.f, +0.f}

    #define TT_STEP(av, cidx) do {                                             \
        float4 mm = *(const float4*)(mb + (cidx) * 16);                        \
        unsigned long long aa, p01, p23;                                       \
        asm("mov.b64 %0, {%1, %2};" : "=l"(aa)  : "f"(av),  "f"(av));          \
        asm("mov.b64 %0, {%1, %2};" : "=l"(p01) : "f"(mm.x), "f"(mm.y));       \
        asm("mov.b64 %0, {%1, %2};" : "=l"(p23) : "f"(mm.z), "f"(mm.w));       \
        asm("fma.rn.f32x2 %0, %1, %2, %0;" : "+l"(acc01) : "l"(aa), "l"(p01)); \
        asm("fma.rn.f32x2 %0, %1, %2, %0;" : "+l"(acc23) : "l"(aa), "l"(p23)); \
    } while (0)

    #pragma unroll
    for (int cb = 0; cb < 16; cb += 4) {
        float4 a = *(const float4*)(rowp + cb);   // conflict-free (stride 20)
        TT_STEP(a.x, cb + 0);
        TT_STEP(a.y, cb + 1);
        TT_STEP(a.z, cb + 2);
        TT_STEP(a.w, cb + 3);
    }
    #undef TT_STEP

    float o0, o1, o2, o3;
    asm("mov.b64 {%0, %1}, %2;" : "=f"(o0), "=f"(o1) : "l"(acc01));
    asm("mov.b64 {%0, %1}, %2;" : "=f"(o2), "=f"(o3) : "l"(acc23));

    // e = xy*16 + zq*4 + j  ->  float4 slot = xy*4 + zq = tid
    ((float4*)(out + (size_t)t * 1024))[tid] = make_float4(o0, o1, o2, o3);
}

// ---------------------------------------------------------------------------
extern "C" void kernel_launch(void* const* d_in, const int* in_sizes, int n_in,
                              void* d_out, int out_size) {
    const float*    c0  = (const float*)d_in[0];
    const float*    c1  = (const float*)d_in[1];
    const float*    c2  = (const float*)d_in[2];
    const unsigned* ids = (const unsigned*)d_in[3];
    float* out = (float*)d_out;

    const int n_tok   = in_sizes[3];          // 16384 element count
    const int n_pairs = n_tok / 2;            // scan only first half: no OOB
    const int n_det   = (n_pairs + 255) / 256;

    tt_build_pq_kernel<<<NP * NQ, 256>>>(c0, c1, ids, n_pairs, n_det);
    tt_gather_kernel<<<n_tok, 256>>>(c2, ids, out);
}

// round 7
// speedup vs baseline: 1.6501x; 1.6501x over previous
#include <cuda_runtime.h>

// ---------------------------------------------------------------------------
// TT-Embedding on GB300 (sm_103a):
//   IN_MODES (40,32,25) -> V=32000;  OUT_MODES (8,8,16) -> E=1024; ranks 16,16
//   out[t,e], e = xy*16 + z;  v -> (p = v/800, q = (v/25)%32, r = v%25)
//   PQ[p,q][xy][c] = sum_b core0[x,p,b]*core1[b,y,q,c]   (5.24 MB, L2-resident)
//   M2T[r][c*16+z] = core2[c,z,r]                        (25.6 KB)
//   out = PQ_slice (64x16) @ M2_r (16x16)   per token
// ---------------------------------------------------------------------------

#define NP 40
#define NQ 32
#define NR 25

__device__ float    g_PQ[NP * NQ * 1024];   // [pq][xy*16 + c]
__device__ float    g_M2T[NR * 256];        // [r][c*16 + z]  (coalesced rows)
__device__ int      g_is64;
__device__ unsigned g_cnt;                  // self-resets via atomicInc wrap
__device__ int      g_part[64];

// ---------------------------------------------------------------------------
// Kernel 1: build PQ table + M2T table + int64 detection.
//   core0: (1,8,40,16)  c0[(x*40+p)*16+b]
//   core1: (16,8,32,16) c1[by*512 + q*16 + c]
//   core2: (16,16,25)   c2[(c*16+z)*25 + r]
// ---------------------------------------------------------------------------
__global__ __launch_bounds__(256) void tt_build_pq_kernel(
    const float* __restrict__ c0, const float* __restrict__ c1,
    const float* __restrict__ c2,
    const unsigned* __restrict__ idw, int n_pairs, int n_det)
{
    const int tid = threadIdx.x;
    const int pq  = blockIdx.x;

    // ---- folded int64 detection (blocks [0, n_det)) ----------------------
    if (pq < n_det) {
        int j   = pq * 256 + tid;
        int bad = (j < n_pairs) && (idw[2 * j + 1] != 0u);
        unsigned m = __ballot_sync(0xffffffffu, bad);
        __shared__ int s_any;
        if (tid == 0) s_any = 0;
        __syncthreads();
        if ((tid & 31) == 0 && m) s_any = 1;
        __syncthreads();
        if (tid == 0) {
            g_part[pq] = s_any;
            __threadfence();
            unsigned old = atomicInc(&g_cnt, (unsigned)(n_det - 1)); // wraps->0
            if (old == (unsigned)(n_det - 1)) {
                int any = 0;
                for (int i = 0; i < n_det; i++) any |= ((volatile int*)g_part)[i];
                g_is64 = !any;
            }
        }
    } else if (pq < n_det + NR) {
        // ---- M2T build (blocks [n_det, n_det+25)) ------------------------
        int r = pq - n_det;
        g_M2T[r * 256 + tid] = c2[tid * NR + r];   // tid == c*16+z
    }

    // ---- main PQ build ----------------------------------------------------
    const int p = pq / NQ;
    const int q = pq % NQ;

    __shared__ float sA[8 * 16];     // A[x][b]
    __shared__ float sM1[128 * 16];  // M1[(b*8+y)][c]

    if (tid < 128) {
        int x = tid >> 4, b = tid & 15;
        sA[tid] = c0[(x * NP + p) * 16 + b];
    }
    #pragma unroll
    for (int i = tid; i < 2048; i += 256) {
        int by = i >> 4, c = i & 15;
        sM1[i] = c1[by * 512 + q * 16 + c];
    }
    __syncthreads();

    #pragma unroll
    for (int k = 0; k < 4; k++) {
        int o  = tid + 256 * k;       // o = xy*16 + c
        int xy = o >> 4;
        int c  = o & 15;
        int x  = xy >> 3;
        int y  = xy & 7;
        float s = 0.f;
        #pragma unroll
        for (int b = 0; b < 16; b++)
            s = fmaf(sA[x * 16 + b], sM1[(b * 8 + y) * 16 + c], s);
        g_PQ[pq * 1024 + o] = s;
    }
}

// ---------------------------------------------------------------------------
// Kernel 2: gather. 4 tokens per block, 64 threads per token.
// Thread (l = tid&63): xyq = l>>2 (0..15), zq = l&3 (0..3).
// Thread outputs: xy in {xyq + 16i, i=0..3}, z in {4zq .. 4zq+3}
//   -> 4 STG.128 at float4 slot (l + 64i): perfectly coalesced.
// Operands: 16 PQ LDS.128 (1 wf each: stride-5-float4 padding covers all 32
// banks) + 16 m2 LDS.128 (broadcast, 1 wf each). f32x2 accumulate: multiplier
// z-pair is free (b64 half of m2 float4); PQ scalar packed {a,a} on alu pipe.
// ---------------------------------------------------------------------------
#define PQ4S 5   // float4 row stride for sPQ (20 floats): conflict-free

__global__ __launch_bounds__(256) void tt_gather_kernel(
    const unsigned* __restrict__ idw, float* __restrict__ out, int n_tok)
{
    const int tid = threadIdx.x;
    const int grp = tid >> 6;                 // token subgroup 0..3
    const int l   = tid & 63;
    const int t   = blockIdx.x * 4 + grp;

    __shared__ float4 sPQ[4][64 * PQ4S];      // 4 x 5 KB (padded rows)
    __shared__ float4 sM2[4][64];             // 4 x 1 KB  [c*4 + zq]

    if (t < n_tok) {
        const unsigned u = g_is64 ? idw[2 * t] : idw[t];
        const unsigned p = u / 800u;
        const unsigned q = (u / 25u) % 32u;
        const unsigned r = u % 25u;

        // stage PQ slice (coalesced LDG.128) into padded smem
        const float4* src = (const float4*)(g_PQ + (p * NQ + q) * 1024);
        #pragma unroll
        for (int k = 0; k < 4; k++) {
            int f = l + 64 * k;               // global float4 idx = xy*4 + cc
            float4 v = src[f];
            sPQ[grp][(f >> 2) * PQ4S + (f & 3)] = v;
        }
        // stage M2 row (coalesced LDG.128)
        sM2[grp][l] = ((const float4*)(g_M2T + r * 256))[l];
    }
    __syncthreads();
    if (t >= n_tok) return;

    const int xyq = l >> 2;
    const int zq  = l & 3;
    const float4* P = sPQ[grp];
    const float4* M = sM2[grp];

    unsigned long long acc[4][2] = {{0ull,0ull},{0ull,0ull},{0ull,0ull},{0ull,0ull}};

    #pragma unroll
    for (int cc = 0; cc < 4; cc++) {
        // m2 float4s for c = 4cc+c', this thread's z quad; b64 halves = z-pairs
        unsigned long long mlo[4], mhi[4];
        #pragma unroll
        for (int cp = 0; cp < 4; cp++) {
            float4 m = M[(4 * cc + cp) * 4 + zq];
            asm("mov.b64 %0, {%1, %2};" : "=l"(mlo[cp]) : "f"(m.x), "f"(m.y));
            asm("mov.b64 %0, {%1, %2};" : "=l"(mhi[cp]) : "f"(m.z), "f"(m.w));
        }
        #pragma unroll
        for (int i = 0; i < 4; i++) {
            float4 a = P[(xyq + 16 * i) * PQ4S + cc];   // PQ[xy][4cc..4cc+3]
            unsigned long long aa;
            #define TT_C(av, cp)                                                   \
                asm("mov.b64 %0, {%1, %2};" : "=l"(aa) : "f"(av), "f"(av));        \
                asm("fma.rn.f32x2 %0, %1, %2, %0;" : "+l"(acc[i][0]) : "l"(aa), "l"(mlo[cp])); \
                asm("fma.rn.f32x2 %0, %1, %2, %0;" : "+l"(acc[i][1]) : "l"(aa), "l"(mhi[cp]));
            TT_C(a.x, 0) TT_C(a.y, 1) TT_C(a.z, 2) TT_C(a.w, 3)
            #undef TT_C
        }
    }

    float4* dst = (float4*)(out + (size_t)t * 1024);
    #pragma unroll
    for (int i = 0; i < 4; i++) {
        float o0, o1, o2, o3;
        asm("mov.b64 {%0, %1}, %2;" : "=f"(o0), "=f"(o1) : "l"(acc[i][0]));
        asm("mov.b64 {%0, %1}, %2;" : "=f"(o2), "=f"(o3) : "l"(acc[i][1]));
        dst[l + 64 * i] = make_float4(o0, o1, o2, o3);  // e = (xyq+16i)*16 + 4zq + j
    }
}

// ---------------------------------------------------------------------------
extern "C" void kernel_launch(void* const* d_in, const int* in_sizes, int n_in,
                              void* d_out, int out_size) {
    const float*    c0  = (const float*)d_in[0];
    const float*    c1  = (const float*)d_in[1];
    const float*    c2  = (const float*)d_in[2];
    const unsigned* ids = (const unsigned*)d_in[3];
    float* out = (float*)d_out;

    const int n_tok   = in_sizes[3];          // element count (16384)
    const int n_pairs = n_tok / 2;            // scan first half only: no OOB
    const int n_det   = (n_pairs + 255) / 256;

    tt_build_pq_kernel<<<NP * NQ, 256>>>(c0, c1, c2, ids, n_pairs, n_det);
    tt_gather_kernel<<<(n_tok + 3) / 4, 256>>>(ids, out, n_tok);
}